// round 1
// baseline (speedup 1.0000x reference)
#include <cuda_runtime.h>
#include <math.h>

#define DM    1024
#define DFF   4096
#define NH    16
#define DH    64
#define BATCH 4
#define SEQ   2048
#define MROWS (BATCH*SEQ)   // 8192

// ---------------- scratch (no allocation allowed) ----------------
static __device__ float g_h  [MROWS*DM];
static __device__ float g_q  [MROWS*DM];
static __device__ float g_k  [MROWS*DM];
static __device__ float g_v  [MROWS*DM];
static __device__ float g_ctx[MROWS*DM];
static __device__ float g_x1 [MROWS*DM];
static __device__ float g_ff [(size_t)MROWS*DFF];

// ---------------- LayerNorm: one block per row of 1024 ----------------
__global__ __launch_bounds__(256) void ln_kernel(
    const float* __restrict__ x, const float* __restrict__ gamma,
    const float* __restrict__ beta, float* __restrict__ out)
{
    const int row = blockIdx.x;
    const int tid = threadIdx.x;
    const float4* xr = (const float4*)(x + (size_t)row * DM);
    float4 v = xr[tid];
    float s  = v.x + v.y + v.z + v.w;
    float ss = v.x*v.x + v.y*v.y + v.z*v.z + v.w*v.w;
    #pragma unroll
    for (int off = 16; off; off >>= 1) {
        s  += __shfl_xor_sync(0xffffffffu, s,  off);
        ss += __shfl_xor_sync(0xffffffffu, ss, off);
    }
    __shared__ float sh[2][8];
    const int w = tid >> 5, lane = tid & 31;
    if (lane == 0) { sh[0][w] = s; sh[1][w] = ss; }
    __syncthreads();
    if (tid < 32) {
        s  = (lane < 8) ? sh[0][lane] : 0.f;
        ss = (lane < 8) ? sh[1][lane] : 0.f;
        #pragma unroll
        for (int off = 4; off; off >>= 1) {
            s  += __shfl_xor_sync(0xffffffffu, s,  off);
            ss += __shfl_xor_sync(0xffffffffu, ss, off);
        }
        if (lane == 0) { sh[0][0] = s; sh[1][0] = ss; }
    }
    __syncthreads();
    s = sh[0][0]; ss = sh[1][0];
    const float mean = s * (1.f/1024.f);
    const float var  = ss * (1.f/1024.f) - mean*mean;
    const float rstd = rsqrtf(var + 1e-5f);
    float4 g  = ((const float4*)gamma)[tid];
    float4 bb = ((const float4*)beta)[tid];
    float4 r;
    r.x = (v.x - mean) * rstd * g.x + bb.x;
    r.y = (v.y - mean) * rstd * g.y + bb.y;
    r.z = (v.z - mean) * rstd * g.z + bb.z;
    r.w = (v.w - mean) * rstd * g.w + bb.w;
    ((float4*)(out + (size_t)row * DM))[tid] = r;
}

// ---------------- SGEMM 128x128x8, 256 threads, 8x8 microtile ----------------
// MODE 0: C = A@B + bias
// MODE 1: QKV relayout: C is [B,H,T,D], value = acc + bias
// MODE 2: exact GELU(acc + bias)
// MODE 3: acc + bias + res[m,n]
// MODE 4: out = xv + gate[b]*(x1v + acc + bias - xv)
template<int MODE>
__global__ __launch_bounds__(256) void sgemm_kernel(
    const float* __restrict__ A, const float* __restrict__ Bm,
    const float* __restrict__ bias, float* __restrict__ C,
    int M, int N, int K,
    const float* __restrict__ res, const float* __restrict__ res2,
    const float* __restrict__ gate)
{
    __shared__ float As[8][128];
    __shared__ float Bs[8][128];
    const int tid = threadIdx.x;
    const int bm = blockIdx.y * 128;
    const int bn = blockIdx.x * 128;
    const int arow = tid >> 1;
    const int acol = (tid & 1) << 2;
    const int brow = tid >> 5;
    const int bcol = (tid & 31) << 2;
    const int tm = (tid >> 4) << 3;
    const int tn = (tid & 15) << 3;
    const float* Aptr = A  + (size_t)(bm + arow) * K + acol;
    const float* Bptr = Bm + (size_t)brow * N + bn + bcol;

    float acc[8][8];
    #pragma unroll
    for (int i = 0; i < 8; i++)
        #pragma unroll
        for (int j = 0; j < 8; j++) acc[i][j] = 0.f;

    for (int k0 = 0; k0 < K; k0 += 8) {
        float4 a4 = *(const float4*)(Aptr + k0);
        float4 b4 = *(const float4*)(Bptr + (size_t)k0 * N);
        As[acol+0][arow] = a4.x;
        As[acol+1][arow] = a4.y;
        As[acol+2][arow] = a4.z;
        As[acol+3][arow] = a4.w;
        *(float4*)&Bs[brow][bcol] = b4;
        __syncthreads();
        #pragma unroll
        for (int k = 0; k < 8; k++) {
            float ar[8], br[8];
            *(float4*)&ar[0] = *(const float4*)&As[k][tm];
            *(float4*)&ar[4] = *(const float4*)&As[k][tm+4];
            *(float4*)&br[0] = *(const float4*)&Bs[k][tn];
            *(float4*)&br[4] = *(const float4*)&Bs[k][tn+4];
            #pragma unroll
            for (int i = 0; i < 8; i++)
                #pragma unroll
                for (int j = 0; j < 8; j++)
                    acc[i][j] += ar[i] * br[j];
        }
        __syncthreads();
    }

    #pragma unroll
    for (int i = 0; i < 8; i++) {
        const int m = bm + tm + i;
        #pragma unroll
        for (int c = 0; c < 8; c += 4) {
            const int n = bn + tn + c;
            float val[4];
            #pragma unroll
            for (int u = 0; u < 4; u++) val[u] = acc[i][c+u] + bias[n+u];
            if (MODE == 1) {
                const int b = m >> 11, t = m & (SEQ-1);
                const int head = n >> 6, d = n & (DH-1);
                float4 v; v.x = val[0]; v.y = val[1]; v.z = val[2]; v.w = val[3];
                *(float4*)(C + (size_t)((b*NH + head)*SEQ + t) * DH + d) = v;
            } else {
                if (MODE == 2) {
                    #pragma unroll
                    for (int u = 0; u < 4; u++)
                        val[u] = 0.5f * val[u] * (1.f + erff(val[u] * 0.70710678118654752f));
                } else if (MODE == 3) {
                    #pragma unroll
                    for (int u = 0; u < 4; u++)
                        val[u] += res[(size_t)m * N + n + u];
                } else if (MODE == 4) {
                    const float gv = gate[m >> 11];
                    #pragma unroll
                    for (int u = 0; u < 4; u++) {
                        const float xv  = res [(size_t)m * N + n + u];
                        const float x1v = res2[(size_t)m * N + n + u];
                        val[u] = xv + gv * (x1v + val[u] - xv);
                    }
                }
                float4 v; v.x = val[0]; v.y = val[1]; v.z = val[2]; v.w = val[3];
                *(float4*)(C + (size_t)m * N + n) = v;
            }
        }
    }
}

// ---------------- Causal flash attention ----------------
// grid: (SEQ/64 query tiles, B*H). 64 threads, one query row each.
__global__ __launch_bounds__(64) void attn_kernel(
    const float* __restrict__ Q, const float* __restrict__ K,
    const float* __restrict__ V, float* __restrict__ ctx)
{
    __shared__ float Ks[64][64];
    __shared__ float Vs[64][64];
    const int qt = blockIdx.x;
    const int bh = blockIdx.y;
    const int b = bh >> 4, h = bh & (NH-1);
    const int tid = threadIdx.x;
    const float* Qb = Q + (size_t)bh * SEQ * DH;
    const float* Kb = K + (size_t)bh * SEQ * DH;
    const float* Vb = V + (size_t)bh * SEQ * DH;
    const int qi = qt * 64 + tid;

    float q[64], o[64];
    #pragma unroll
    for (int d4 = 0; d4 < 16; d4++) {
        float4 v = *(const float4*)(Qb + (size_t)qi * DH + d4*4);
        q[d4*4+0] = v.x * 0.125f;
        q[d4*4+1] = v.y * 0.125f;
        q[d4*4+2] = v.z * 0.125f;
        q[d4*4+3] = v.w * 0.125f;
    }
    #pragma unroll
    for (int d = 0; d < 64; d++) o[d] = 0.f;
    float mrun = -INFINITY, l = 0.f;

    for (int kt = 0; kt <= qt; kt++) {
        __syncthreads();
        #pragma unroll
        for (int i = 0; i < 16; i++) {
            const int idx = i * 64 + tid;          // float4 index within 64x64 tile
            const int j = idx >> 4, d4 = idx & 15;
            *(float4*)&Ks[j][d4*4] = *(const float4*)(Kb + (size_t)(kt*64 + j)*DH + d4*4);
            *(float4*)&Vs[j][d4*4] = *(const float4*)(Vb + (size_t)(kt*64 + j)*DH + d4*4);
        }
        __syncthreads();
        const bool diag = (kt == qt);
        for (int jc = 0; jc < 8; jc++) {
            const int jbase = jc * 8;
            if (diag && jbase > tid) break;
            float s[8];
            float cmax = -INFINITY;
            #pragma unroll
            for (int jj = 0; jj < 8; jj++) {
                const int j = jbase + jj;
                float sv = 0.f;
                #pragma unroll
                for (int d = 0; d < 64; d++) sv += q[d] * Ks[j][d];
                if (diag && j > tid) sv = -INFINITY;
                s[jj] = sv;
                cmax = fmaxf(cmax, sv);
            }
            const float mnew = fmaxf(mrun, cmax);
            const float corr = expf(mrun - mnew);   // exp(-inf)=0 first time
            l *= corr;
            #pragma unroll
            for (int d = 0; d < 64; d++) o[d] *= corr;
            #pragma unroll
            for (int jj = 0; jj < 8; jj++) {
                const int j = jbase + jj;
                const float p = expf(s[jj] - mnew); // masked -> 0
                l += p;
                #pragma unroll
                for (int d = 0; d < 64; d++) o[d] += p * Vs[j][d];
            }
            mrun = mnew;
        }
    }
    const float inv = 1.f / l;
    float* dst = ctx + ((size_t)(b * SEQ + qi) * DM + h * DH);
    #pragma unroll
    for (int d4 = 0; d4 < 16; d4++) {
        float4 v;
        v.x = o[d4*4+0] * inv;
        v.y = o[d4*4+1] * inv;
        v.z = o[d4*4+2] * inv;
        v.w = o[d4*4+3] * inv;
        *(float4*)(dst + d4*4) = v;
    }
}

// ---------------- launch ----------------
extern "C" void kernel_launch(void* const* d_in, const int* in_sizes, int n_in,
                              void* d_out, int out_size)
{
    const float* x      = (const float*)d_in[0];
    const float* gate   = (const float*)d_in[1];
    const float* Wq     = (const float*)d_in[2];
    const float* bq     = (const float*)d_in[3];
    const float* Wk     = (const float*)d_in[4];
    const float* bk     = (const float*)d_in[5];
    const float* Wv     = (const float*)d_in[6];
    const float* bv     = (const float*)d_in[7];
    const float* Wo     = (const float*)d_in[8];
    const float* bo     = (const float*)d_in[9];
    const float* W1     = (const float*)d_in[10];
    const float* b1     = (const float*)d_in[11];
    const float* W2     = (const float*)d_in[12];
    const float* b2     = (const float*)d_in[13];
    const float* gamma1 = (const float*)d_in[14];
    const float* beta1  = (const float*)d_in[15];
    const float* gamma2 = (const float*)d_in[16];
    const float* beta2  = (const float*)d_in[17];
    float* out = (float*)d_out;

    float *h, *q, *k, *v, *ctx, *x1, *ff;
    cudaGetSymbolAddress((void**)&h,   g_h);
    cudaGetSymbolAddress((void**)&q,   g_q);
    cudaGetSymbolAddress((void**)&k,   g_k);
    cudaGetSymbolAddress((void**)&v,   g_v);
    cudaGetSymbolAddress((void**)&ctx, g_ctx);
    cudaGetSymbolAddress((void**)&x1,  g_x1);
    cudaGetSymbolAddress((void**)&ff,  g_ff);

    // 1. h = LN(x)
    ln_kernel<<<MROWS, 256>>>(x, gamma1, beta1, h);

    // 2. Q/K/V projections with fused [B,H,T,D] relayout
    dim3 g1(DM/128, MROWS/128);
    sgemm_kernel<1><<<g1, 256>>>(h, Wq, bq, q, MROWS, DM, DM, nullptr, nullptr, nullptr);
    sgemm_kernel<1><<<g1, 256>>>(h, Wk, bk, k, MROWS, DM, DM, nullptr, nullptr, nullptr);
    sgemm_kernel<1><<<g1, 256>>>(h, Wv, bv, v, MROWS, DM, DM, nullptr, nullptr, nullptr);

    // 3. causal attention -> ctx [B,T,C]
    attn_kernel<<<dim3(SEQ/64, BATCH*NH), 64>>>(q, k, v, ctx);

    // 4. x1 = ctx@Wo + bo + x
    sgemm_kernel<3><<<g1, 256>>>(ctx, Wo, bo, x1, MROWS, DM, DM, x, nullptr, nullptr);

    // 5. h = LN(x1)   (reuse h)
    ln_kernel<<<MROWS, 256>>>(x1, gamma2, beta2, h);

    // 6. ff = GELU(h@W1 + b1)
    sgemm_kernel<2><<<dim3(DFF/128, MROWS/128), 256>>>(h, W1, b1, ff, MROWS, DFF, DM,
                                                       nullptr, nullptr, nullptr);

    // 7. out = x + g*(x1 + (ff@W2 + b2) - x)
    sgemm_kernel<4><<<g1, 256>>>(ff, W2, b2, out, MROWS, DM, DFF, x, x1, gate);
}

// round 8
// speedup vs baseline: 1.9995x; 1.9995x over previous
#include <cuda_runtime.h>
#include <cuda_bf16.h>
#include <math.h>
#include <stdint.h>

#define DM    1024
#define DFF   4096
#define NH    16
#define DH    64
#define BATCH 4
#define SEQ   2048
#define MROWS (BATCH*SEQ)   // 8192

// ---------------- scratch (no allocation allowed) ----------------
static __device__ float g_h  [MROWS*DM];
static __device__ float g_q  [MROWS*DM];
static __device__ float g_k  [MROWS*DM];
static __device__ float g_v  [MROWS*DM];
static __device__ float g_ctx[MROWS*DM];
static __device__ float g_x1 [MROWS*DM];
static __device__ float g_ff [(size_t)MROWS*DFF];

// ================= helpers =================
__device__ __forceinline__ uint32_t smem_u32(const void* p) {
    uint32_t a;
    asm("{ .reg .u64 t; cvta.to.shared.u64 t, %1; cvt.u32.u64 %0, t; }" : "=r"(a) : "l"(p));
    return a;
}
__device__ __forceinline__ void mma_bf16(float* c, const uint32_t* a, uint32_t b0, uint32_t b1) {
    asm volatile(
        "mma.sync.aligned.m16n8k16.row.col.f32.bf16.bf16.f32 "
        "{%0,%1,%2,%3}, {%4,%5,%6,%7}, {%8,%9}, {%0,%1,%2,%3};"
        : "+f"(c[0]), "+f"(c[1]), "+f"(c[2]), "+f"(c[3])
        : "r"(a[0]), "r"(a[1]), "r"(a[2]), "r"(a[3]), "r"(b0), "r"(b1));
}
__device__ __forceinline__ void ldmatrix_x4t(uint32_t* r, uint32_t addr) {
    asm volatile("ldmatrix.sync.aligned.m8n8.x4.trans.shared.b16 {%0,%1,%2,%3}, [%4];"
                 : "=r"(r[0]), "=r"(r[1]), "=r"(r[2]), "=r"(r[3]) : "r"(addr));
}
__device__ __forceinline__ uint32_t bf2_u32(__nv_bfloat162 v) { return *(uint32_t*)&v; }

// ---------------- LayerNorm: one block per row of 1024 ----------------
__global__ __launch_bounds__(256) void ln_kernel(
    const float* __restrict__ x, const float* __restrict__ gamma,
    const float* __restrict__ beta, float* __restrict__ out)
{
    const int row = blockIdx.x;
    const int tid = threadIdx.x;
    const float4* xr = (const float4*)(x + (size_t)row * DM);
    float4 v = xr[tid];
    float s  = v.x + v.y + v.z + v.w;
    float ss = v.x*v.x + v.y*v.y + v.z*v.z + v.w*v.w;
    #pragma unroll
    for (int off = 16; off; off >>= 1) {
        s  += __shfl_xor_sync(0xffffffffu, s,  off);
        ss += __shfl_xor_sync(0xffffffffu, ss, off);
    }
    __shared__ float sh[2][8];
    const int w = tid >> 5, lane = tid & 31;
    if (lane == 0) { sh[0][w] = s; sh[1][w] = ss; }
    __syncthreads();
    if (tid < 32) {
        s  = (lane < 8) ? sh[0][lane] : 0.f;
        ss = (lane < 8) ? sh[1][lane] : 0.f;
        #pragma unroll
        for (int off = 4; off; off >>= 1) {
            s  += __shfl_xor_sync(0xffffffffu, s,  off);
            ss += __shfl_xor_sync(0xffffffffu, ss, off);
        }
        if (lane == 0) { sh[0][0] = s; sh[1][0] = ss; }
    }
    __syncthreads();
    s = sh[0][0]; ss = sh[1][0];
    const float mean = s * (1.f/1024.f);
    const float var  = ss * (1.f/1024.f) - mean*mean;
    const float rstd = rsqrtf(var + 1e-5f);
    float4 g  = ((const float4*)gamma)[tid];
    float4 bb = ((const float4*)beta)[tid];
    float4 r;
    r.x = (v.x - mean) * rstd * g.x + bb.x;
    r.y = (v.y - mean) * rstd * g.y + bb.y;
    r.z = (v.z - mean) * rstd * g.z + bb.z;
    r.w = (v.w - mean) * rstd * g.w + bb.w;
    ((float4*)(out + (size_t)row * DM))[tid] = r;
}

// ============ mma.sync split-bf16 GEMM: 128x128 tile, 8 warps, K chunks of 64 ============
// smem: A hi/lo [128][72] bf16 (row stride 144B), B hi/lo [64][136] bf16 (row stride 272B)
#define SA_HI 0
#define SA_LO 18432
#define SB_HI 36864
#define SB_LO 54272
#define SMEM_BYTES 71680

template<int MODE>
__global__ void __launch_bounds__(256, 2) mma_gemm(
    const float* __restrict__ A, const float* __restrict__ B,
    const float* __restrict__ bias, float* __restrict__ C,
    int M, int N, int K,
    const float* __restrict__ res, const float* __restrict__ res2,
    const float* __restrict__ gate)
{
    extern __shared__ char smem[];
    const uint32_t sb = smem_u32(smem);
    const int tid  = threadIdx.x;
    const int lane = tid & 31, wid = tid >> 5;
    const int bm = blockIdx.y * 128, bn = blockIdx.x * 128;
    const int wm = (wid & 3) * 32;     // warp m offset within tile
    const int wn = (wid >> 2) * 64;    // warp n offset within tile

    const int lr4 = lane >> 2, lc4 = lane & 3;
    // ldmatrix.x4.trans lane mapping for B (reg order: (k0,n0),(k0+8,n0),(k0,n0+8),(k0+8,n0+8))
    const int g = lane >> 3, lr8 = lane & 7;
    const int b_krow = lr8 + (g & 1) * 8;
    const int b_ncol = (g >> 1) * 8;

    float acc[2][8][4];
    #pragma unroll
    for (int a = 0; a < 2; a++)
        #pragma unroll
        for (int b = 0; b < 8; b++)
            #pragma unroll
            for (int c = 0; c < 4; c++) acc[a][b][c] = 0.f;

    const int nchunk = K >> 6;
    for (int ch = 0; ch < nchunk; ch++) {
        const int k0 = ch << 6;
        // ---- A chunk [128 x 64] fp32 -> hi/lo bf16 smem (stride 72 el) ----
        #pragma unroll
        for (int i = 0; i < 8; i++) {
            const int idx = i * 256 + tid;
            const int r = idx >> 4, c4 = idx & 15;
            float4 a = *(const float4*)(A + (size_t)(bm + r) * K + k0 + c4 * 4);
            __nv_bfloat162 h0 = __float22bfloat162_rn(make_float2(a.x, a.y));
            __nv_bfloat162 h1 = __float22bfloat162_rn(make_float2(a.z, a.w));
            float2 hf0 = __bfloat1622float2(h0), hf1 = __bfloat1622float2(h1);
            __nv_bfloat162 l0 = __float22bfloat162_rn(make_float2(a.x - hf0.x, a.y - hf0.y));
            __nv_bfloat162 l1 = __float22bfloat162_rn(make_float2(a.z - hf1.x, a.w - hf1.y));
            const uint32_t off = (uint32_t)(r * 144 + c4 * 8);
            *(uint2*)(smem + SA_HI + off) = make_uint2(bf2_u32(h0), bf2_u32(h1));
            *(uint2*)(smem + SA_LO + off) = make_uint2(bf2_u32(l0), bf2_u32(l1));
        }
        // ---- B chunk [64 x 128] fp32 -> hi/lo bf16 smem row-major (stride 136 el) ----
        #pragma unroll
        for (int i = 0; i < 8; i++) {
            const int idx = i * 256 + tid;
            const int kr = idx >> 5, nc4 = idx & 31;
            float4 b = *(const float4*)(B + (size_t)(k0 + kr) * N + bn + nc4 * 4);
            __nv_bfloat162 h0 = __float22bfloat162_rn(make_float2(b.x, b.y));
            __nv_bfloat162 h1 = __float22bfloat162_rn(make_float2(b.z, b.w));
            float2 hf0 = __bfloat1622float2(h0), hf1 = __bfloat1622float2(h1);
            __nv_bfloat162 l0 = __float22bfloat162_rn(make_float2(b.x - hf0.x, b.y - hf0.y));
            __nv_bfloat162 l1 = __float22bfloat162_rn(make_float2(b.z - hf1.x, b.w - hf1.y));
            const uint32_t off = (uint32_t)(kr * 272 + nc4 * 8);
            *(uint2*)(smem + SB_HI + off) = make_uint2(bf2_u32(h0), bf2_u32(h1));
            *(uint2*)(smem + SB_LO + off) = make_uint2(bf2_u32(l0), bf2_u32(l1));
        }
        __syncthreads();

        #pragma unroll
        for (int ks = 0; ks < 4; ks++) {
            // A fragments (hi/lo) for both m16 tiles: 4 x LDS.32 each, conflict-free
            uint32_t ah[2][4], al[2][4];
            #pragma unroll
            for (int mt = 0; mt < 2; mt++) {
                const uint32_t r0 = (uint32_t)((wm + mt * 16 + lr4) * 144 + ks * 32 + lc4 * 4);
                ah[mt][0] = *(const uint32_t*)(smem + SA_HI + r0);
                ah[mt][1] = *(const uint32_t*)(smem + SA_HI + r0 + 8 * 144);
                ah[mt][2] = *(const uint32_t*)(smem + SA_HI + r0 + 16);
                ah[mt][3] = *(const uint32_t*)(smem + SA_HI + r0 + 8 * 144 + 16);
                al[mt][0] = *(const uint32_t*)(smem + SA_LO + r0);
                al[mt][1] = *(const uint32_t*)(smem + SA_LO + r0 + 8 * 144);
                al[mt][2] = *(const uint32_t*)(smem + SA_LO + r0 + 16);
                al[mt][3] = *(const uint32_t*)(smem + SA_LO + r0 + 8 * 144 + 16);
            }
            #pragma unroll
            for (int p = 0; p < 4; p++) {
                const uint32_t baddr = sb + SB_HI
                    + (uint32_t)((ks * 16 + b_krow) * 272 + (wn + p * 16 + b_ncol) * 2);
                uint32_t bh[4], bl[4];
                ldmatrix_x4t(bh, baddr);
                ldmatrix_x4t(bl, baddr + (SB_LO - SB_HI));
                #pragma unroll
                for (int mt = 0; mt < 2; mt++) {
                    mma_bf16(acc[mt][2*p],   ah[mt], bh[0], bh[1]);
                    mma_bf16(acc[mt][2*p+1], ah[mt], bh[2], bh[3]);
                }
                #pragma unroll
                for (int mt = 0; mt < 2; mt++) {
                    mma_bf16(acc[mt][2*p],   ah[mt], bl[0], bl[1]);
                    mma_bf16(acc[mt][2*p+1], ah[mt], bl[2], bl[3]);
                }
                #pragma unroll
                for (int mt = 0; mt < 2; mt++) {
                    mma_bf16(acc[mt][2*p],   al[mt], bh[0], bh[1]);
                    mma_bf16(acc[mt][2*p+1], al[mt], bh[2], bh[3]);
                }
            }
        }
        __syncthreads();
    }

    // ---- epilogue from register accumulators ----
    #pragma unroll
    for (int mt = 0; mt < 2; mt++) {
        #pragma unroll
        for (int half = 0; half < 2; half++) {
            const int m = bm + wm + mt * 16 + half * 8 + lr4;
            #pragma unroll
            for (int nt = 0; nt < 8; nt++) {
                const int n = bn + wn + nt * 8 + lc4 * 2;
                float v0 = acc[mt][nt][half * 2 + 0] + bias[n];
                float v1 = acc[mt][nt][half * 2 + 1] + bias[n + 1];
                if (MODE == 1) {
                    const int b = m >> 11, t = m & (SEQ - 1);
                    const int head = n >> 6, d = n & (DH - 1);
                    float2 v; v.x = v0; v.y = v1;
                    *(float2*)(C + (size_t)((b * NH + head) * SEQ + t) * DH + d) = v;
                } else {
                    if (MODE == 2) {
                        v0 = 0.5f * v0 * (1.f + erff(v0 * 0.70710678118654752f));
                        v1 = 0.5f * v1 * (1.f + erff(v1 * 0.70710678118654752f));
                    } else if (MODE == 3) {
                        float2 rv = *(const float2*)(res + (size_t)m * N + n);
                        v0 += rv.x; v1 += rv.y;
                    } else if (MODE == 4) {
                        const float gv = gate[m >> 11];
                        float2 xv  = *(const float2*)(res  + (size_t)m * N + n);
                        float2 x1v = *(const float2*)(res2 + (size_t)m * N + n);
                        v0 = xv.x + gv * (x1v.x + v0 - xv.x);
                        v1 = xv.y + gv * (x1v.y + v1 - xv.y);
                    }
                    float2 v; v.x = v0; v.y = v1;
                    *(float2*)(C + (size_t)m * N + n) = v;
                }
            }
        }
    }
}

// ---------------- Causal flash attention ----------------
__global__ __launch_bounds__(64) void attn_kernel(
    const float* __restrict__ Q, const float* __restrict__ K,
    const float* __restrict__ V, float* __restrict__ ctx)
{
    __shared__ float Ks[64][64];
    __shared__ float Vs[64][64];
    const int qt = blockIdx.x;
    const int bh = blockIdx.y;
    const int b = bh >> 4, h = bh & (NH-1);
    const int tid = threadIdx.x;
    const float* Qb = Q + (size_t)bh * SEQ * DH;
    const float* Kb = K + (size_t)bh * SEQ * DH;
    const float* Vb = V + (size_t)bh * SEQ * DH;
    const int qi = qt * 64 + tid;

    float q[64], o[64];
    #pragma unroll
    for (int d4 = 0; d4 < 16; d4++) {
        float4 v = *(const float4*)(Qb + (size_t)qi * DH + d4*4);
        q[d4*4+0] = v.x * 0.125f;
        q[d4*4+1] = v.y * 0.125f;
        q[d4*4+2] = v.z * 0.125f;
        q[d4*4+3] = v.w * 0.125f;
    }
    #pragma unroll
    for (int d = 0; d < 64; d++) o[d] = 0.f;
    float mrun = -INFINITY, l = 0.f;

    for (int kt = 0; kt <= qt; kt++) {
        __syncthreads();
        #pragma unroll
        for (int i = 0; i < 16; i++) {
            const int idx = i * 64 + tid;
            const int j = idx >> 4, d4 = idx & 15;
            *(float4*)&Ks[j][d4*4] = *(const float4*)(Kb + (size_t)(kt*64 + j)*DH + d4*4);
            *(float4*)&Vs[j][d4*4] = *(const float4*)(Vb + (size_t)(kt*64 + j)*DH + d4*4);
        }
        __syncthreads();
        const bool diag = (kt == qt);
        for (int jc = 0; jc < 8; jc++) {
            const int jbase = jc * 8;
            if (diag && jbase > tid) break;
            float s[8];
            float cmax = -INFINITY;
            #pragma unroll
            for (int jj = 0; jj < 8; jj++) {
                const int j = jbase + jj;
                float sv = 0.f;
                #pragma unroll
                for (int d = 0; d < 64; d++) sv += q[d] * Ks[j][d];
                if (diag && j > tid) sv = -INFINITY;
                s[jj] = sv;
                cmax = fmaxf(cmax, sv);
            }
            const float mnew = fmaxf(mrun, cmax);
            const float corr = expf(mrun - mnew);
            l *= corr;
            #pragma unroll
            for (int d = 0; d < 64; d++) o[d] *= corr;
            #pragma unroll
            for (int jj = 0; jj < 8; jj++) {
                const int j = jbase + jj;
                const float p = expf(s[jj] - mnew);
                l += p;
                #pragma unroll
                for (int d = 0; d < 64; d++) o[d] += p * Vs[j][d];
            }
            mrun = mnew;
        }
    }
    const float inv = 1.f / l;
    float* dst = ctx + ((size_t)(b * SEQ + qi) * DM + h * DH);
    #pragma unroll
    for (int d4 = 0; d4 < 16; d4++) {
        float4 v;
        v.x = o[d4*4+0] * inv;
        v.y = o[d4*4+1] * inv;
        v.z = o[d4*4+2] * inv;
        v.w = o[d4*4+3] * inv;
        *(float4*)(dst + d4*4) = v;
    }
}

// ---------------- launch ----------------
extern "C" void kernel_launch(void* const* d_in, const int* in_sizes, int n_in,
                              void* d_out, int out_size)
{
    const float* x      = (const float*)d_in[0];
    const float* gate   = (const float*)d_in[1];
    const float* Wq     = (const float*)d_in[2];
    const float* bq     = (const float*)d_in[3];
    const float* Wk     = (const float*)d_in[4];
    const float* bk     = (const float*)d_in[5];
    const float* Wv     = (const float*)d_in[6];
    const float* bv     = (const float*)d_in[7];
    const float* Wo     = (const float*)d_in[8];
    const float* bo     = (const float*)d_in[9];
    const float* W1     = (const float*)d_in[10];
    const float* b1     = (const float*)d_in[11];
    const float* W2     = (const float*)d_in[12];
    const float* b2     = (const float*)d_in[13];
    const float* gamma1 = (const float*)d_in[14];
    const float* beta1  = (const float*)d_in[15];
    const float* gamma2 = (const float*)d_in[16];
    const float* beta2  = (const float*)d_in[17];
    float* out = (float*)d_out;

    float *h, *q, *k, *v, *ctx, *x1, *ff;
    cudaGetSymbolAddress((void**)&h,   g_h);
    cudaGetSymbolAddress((void**)&q,   g_q);
    cudaGetSymbolAddress((void**)&k,   g_k);
    cudaGetSymbolAddress((void**)&v,   g_v);
    cudaGetSymbolAddress((void**)&ctx, g_ctx);
    cudaGetSymbolAddress((void**)&x1,  g_x1);
    cudaGetSymbolAddress((void**)&ff,  g_ff);

    cudaFuncSetAttribute(mma_gemm<1>, cudaFuncAttributeMaxDynamicSharedMemorySize, SMEM_BYTES);
    cudaFuncSetAttribute(mma_gemm<2>, cudaFuncAttributeMaxDynamicSharedMemorySize, SMEM_BYTES);
    cudaFuncSetAttribute(mma_gemm<3>, cudaFuncAttributeMaxDynamicSharedMemorySize, SMEM_BYTES);
    cudaFuncSetAttribute(mma_gemm<4>, cudaFuncAttributeMaxDynamicSharedMemorySize, SMEM_BYTES);

    // 1. h = LN(x)
    ln_kernel<<<MROWS, 256>>>(x, gamma1, beta1, h);

    // 2. Q/K/V projections with fused [B,H,T,D] relayout
    dim3 g1(DM/128, MROWS/128);
    mma_gemm<1><<<g1, 256, SMEM_BYTES>>>(h, Wq, bq, q, MROWS, DM, DM, nullptr, nullptr, nullptr);
    mma_gemm<1><<<g1, 256, SMEM_BYTES>>>(h, Wk, bk, k, MROWS, DM, DM, nullptr, nullptr, nullptr);
    mma_gemm<1><<<g1, 256, SMEM_BYTES>>>(h, Wv, bv, v, MROWS, DM, DM, nullptr, nullptr, nullptr);

    // 3. causal attention -> ctx [B,T,C]
    attn_kernel<<<dim3(SEQ/64, BATCH*NH), 64>>>(q, k, v, ctx);

    // 4. x1 = ctx@Wo + bo + x
    mma_gemm<3><<<g1, 256, SMEM_BYTES>>>(ctx, Wo, bo, x1, MROWS, DM, DM, x, nullptr, nullptr);

    // 5. h = LN(x1)
    ln_kernel<<<MROWS, 256>>>(x1, gamma2, beta2, h);

    // 6. ff = GELU(h@W1 + b1)
    mma_gemm<2><<<dim3(DFF/128, MROWS/128), 256, SMEM_BYTES>>>(h, W1, b1, ff, MROWS, DFF, DM,
                                                               nullptr, nullptr, nullptr);

    // 7. out = x + g*(x1 + (ff@W2 + b2) - x)
    mma_gemm<4><<<g1, 256, SMEM_BYTES>>>(ff, W2, b2, out, MROWS, DM, DFF, x, x1, gate);
}

// round 9
// speedup vs baseline: 2.9872x; 1.4939x over previous
#include <cuda_runtime.h>
#include <cuda_bf16.h>
#include <math.h>
#include <stdint.h>

#define DM    1024
#define DFF   4096
#define NH    16
#define DH    64
#define BATCH 4
#define SEQ   2048
#define MROWS (BATCH*SEQ)   // 8192

// ---------------- scratch (no allocation allowed) ----------------
static __device__ float g_h  [MROWS*DM];
static __device__ float g_q  [MROWS*DM];
static __device__ float g_k  [MROWS*DM];
static __device__ float g_v  [MROWS*DM];
static __device__ float g_ctx[MROWS*DM];
static __device__ float g_x1 [MROWS*DM];
static __device__ float g_ff [(size_t)MROWS*DFF];

// ================= helpers =================
__device__ __forceinline__ uint32_t smem_u32(const void* p) {
    uint32_t a;
    asm("{ .reg .u64 t; cvta.to.shared.u64 t, %1; cvt.u32.u64 %0, t; }" : "=r"(a) : "l"(p));
    return a;
}
__device__ __forceinline__ void mma_bf16(float* c, const uint32_t* a, uint32_t b0, uint32_t b1) {
    asm volatile(
        "mma.sync.aligned.m16n8k16.row.col.f32.bf16.bf16.f32 "
        "{%0,%1,%2,%3}, {%4,%5,%6,%7}, {%8,%9}, {%0,%1,%2,%3};"
        : "+f"(c[0]), "+f"(c[1]), "+f"(c[2]), "+f"(c[3])
        : "r"(a[0]), "r"(a[1]), "r"(a[2]), "r"(a[3]), "r"(b0), "r"(b1));
}
__device__ __forceinline__ void ldmatrix_x4t(uint32_t* r, uint32_t addr) {
    asm volatile("ldmatrix.sync.aligned.m8n8.x4.trans.shared.b16 {%0,%1,%2,%3}, [%4];"
                 : "=r"(r[0]), "=r"(r[1]), "=r"(r[2]), "=r"(r[3]) : "r"(addr));
}
__device__ __forceinline__ void ldmatrix_x4(uint32_t* r, uint32_t addr) {
    asm volatile("ldmatrix.sync.aligned.m8n8.x4.shared.b16 {%0,%1,%2,%3}, [%4];"
                 : "=r"(r[0]), "=r"(r[1]), "=r"(r[2]), "=r"(r[3]) : "r"(addr));
}
__device__ __forceinline__ uint32_t bf2_u32(__nv_bfloat162 v) { return *(uint32_t*)&v; }

// ---------------- LayerNorm: one block per row of 1024 ----------------
__global__ __launch_bounds__(256) void ln_kernel(
    const float* __restrict__ x, const float* __restrict__ gamma,
    const float* __restrict__ beta, float* __restrict__ out)
{
    const int row = blockIdx.x;
    const int tid = threadIdx.x;
    const float4* xr = (const float4*)(x + (size_t)row * DM);
    float4 v = xr[tid];
    float s  = v.x + v.y + v.z + v.w;
    float ss = v.x*v.x + v.y*v.y + v.z*v.z + v.w*v.w;
    #pragma unroll
    for (int off = 16; off; off >>= 1) {
        s  += __shfl_xor_sync(0xffffffffu, s,  off);
        ss += __shfl_xor_sync(0xffffffffu, ss, off);
    }
    __shared__ float sh[2][8];
    const int w = tid >> 5, lane = tid & 31;
    if (lane == 0) { sh[0][w] = s; sh[1][w] = ss; }
    __syncthreads();
    if (tid < 32) {
        s  = (lane < 8) ? sh[0][lane] : 0.f;
        ss = (lane < 8) ? sh[1][lane] : 0.f;
        #pragma unroll
        for (int off = 4; off; off >>= 1) {
            s  += __shfl_xor_sync(0xffffffffu, s,  off);
            ss += __shfl_xor_sync(0xffffffffu, ss, off);
        }
        if (lane == 0) { sh[0][0] = s; sh[1][0] = ss; }
    }
    __syncthreads();
    s = sh[0][0]; ss = sh[1][0];
    const float mean = s * (1.f/1024.f);
    const float var  = ss * (1.f/1024.f) - mean*mean;
    const float rstd = rsqrtf(var + 1e-5f);
    float4 g  = ((const float4*)gamma)[tid];
    float4 bb = ((const float4*)beta)[tid];
    float4 r;
    r.x = (v.x - mean) * rstd * g.x + bb.x;
    r.y = (v.y - mean) * rstd * g.y + bb.y;
    r.z = (v.z - mean) * rstd * g.z + bb.z;
    r.w = (v.w - mean) * rstd * g.w + bb.w;
    ((float4*)(out + (size_t)row * DM))[tid] = r;
}

// ============ mma.sync split-bf16 GEMM: 128x128 tile, 8 warps, K chunks of 64 ============
#define SA_HI 0
#define SA_LO 18432
#define SB_HI 36864
#define SB_LO 54272
#define SMEM_BYTES 71680

template<int MODE>
__global__ void __launch_bounds__(256, 2) mma_gemm(
    const float* __restrict__ A, const float* __restrict__ B,
    const float* __restrict__ bias, float* __restrict__ C,
    int M, int N, int K,
    const float* __restrict__ res, const float* __restrict__ res2,
    const float* __restrict__ gate)
{
    extern __shared__ char smem[];
    const uint32_t sb = smem_u32(smem);
    const int tid  = threadIdx.x;
    const int lane = tid & 31, wid = tid >> 5;
    const int bm = blockIdx.y * 128, bn = blockIdx.x * 128;
    const int wm = (wid & 3) * 32;
    const int wn = (wid >> 2) * 64;

    const int lr4 = lane >> 2, lc4 = lane & 3;
    const int g = lane >> 3, lr8 = lane & 7;
    const int b_krow = lr8 + (g & 1) * 8;
    const int b_ncol = (g >> 1) * 8;

    float acc[2][8][4];
    #pragma unroll
    for (int a = 0; a < 2; a++)
        #pragma unroll
        for (int b = 0; b < 8; b++)
            #pragma unroll
            for (int c = 0; c < 4; c++) acc[a][b][c] = 0.f;

    const int nchunk = K >> 6;
    for (int ch = 0; ch < nchunk; ch++) {
        const int k0 = ch << 6;
        #pragma unroll
        for (int i = 0; i < 8; i++) {
            const int idx = i * 256 + tid;
            const int r = idx >> 4, c4 = idx & 15;
            float4 a = *(const float4*)(A + (size_t)(bm + r) * K + k0 + c4 * 4);
            __nv_bfloat162 h0 = __float22bfloat162_rn(make_float2(a.x, a.y));
            __nv_bfloat162 h1 = __float22bfloat162_rn(make_float2(a.z, a.w));
            float2 hf0 = __bfloat1622float2(h0), hf1 = __bfloat1622float2(h1);
            __nv_bfloat162 l0 = __float22bfloat162_rn(make_float2(a.x - hf0.x, a.y - hf0.y));
            __nv_bfloat162 l1 = __float22bfloat162_rn(make_float2(a.z - hf1.x, a.w - hf1.y));
            const uint32_t off = (uint32_t)(r * 144 + c4 * 8);
            *(uint2*)(smem + SA_HI + off) = make_uint2(bf2_u32(h0), bf2_u32(h1));
            *(uint2*)(smem + SA_LO + off) = make_uint2(bf2_u32(l0), bf2_u32(l1));
        }
        #pragma unroll
        for (int i = 0; i < 8; i++) {
            const int idx = i * 256 + tid;
            const int kr = idx >> 5, nc4 = idx & 31;
            float4 b = *(const float4*)(B + (size_t)(k0 + kr) * N + bn + nc4 * 4);
            __nv_bfloat162 h0 = __float22bfloat162_rn(make_float2(b.x, b.y));
            __nv_bfloat162 h1 = __float22bfloat162_rn(make_float2(b.z, b.w));
            float2 hf0 = __bfloat1622float2(h0), hf1 = __bfloat1622float2(h1);
            __nv_bfloat162 l0 = __float22bfloat162_rn(make_float2(b.x - hf0.x, b.y - hf0.y));
            __nv_bfloat162 l1 = __float22bfloat162_rn(make_float2(b.z - hf1.x, b.w - hf1.y));
            const uint32_t off = (uint32_t)(kr * 272 + nc4 * 8);
            *(uint2*)(smem + SB_HI + off) = make_uint2(bf2_u32(h0), bf2_u32(h1));
            *(uint2*)(smem + SB_LO + off) = make_uint2(bf2_u32(l0), bf2_u32(l1));
        }
        __syncthreads();

        #pragma unroll
        for (int ks = 0; ks < 4; ks++) {
            uint32_t ah[2][4], al[2][4];
            #pragma unroll
            for (int mt = 0; mt < 2; mt++) {
                const uint32_t r0 = (uint32_t)((wm + mt * 16 + lr4) * 144 + ks * 32 + lc4 * 4);
                ah[mt][0] = *(const uint32_t*)(smem + SA_HI + r0);
                ah[mt][1] = *(const uint32_t*)(smem + SA_HI + r0 + 8 * 144);
                ah[mt][2] = *(const uint32_t*)(smem + SA_HI + r0 + 16);
                ah[mt][3] = *(const uint32_t*)(smem + SA_HI + r0 + 8 * 144 + 16);
                al[mt][0] = *(const uint32_t*)(smem + SA_LO + r0);
                al[mt][1] = *(const uint32_t*)(smem + SA_LO + r0 + 8 * 144);
                al[mt][2] = *(const uint32_t*)(smem + SA_LO + r0 + 16);
                al[mt][3] = *(const uint32_t*)(smem + SA_LO + r0 + 8 * 144 + 16);
            }
            #pragma unroll
            for (int p = 0; p < 4; p++) {
                const uint32_t baddr = sb + SB_HI
                    + (uint32_t)((ks * 16 + b_krow) * 272 + (wn + p * 16 + b_ncol) * 2);
                uint32_t bh[4], bl[4];
                ldmatrix_x4t(bh, baddr);
                ldmatrix_x4t(bl, baddr + (SB_LO - SB_HI));
                #pragma unroll
                for (int mt = 0; mt < 2; mt++) {
                    mma_bf16(acc[mt][2*p],   ah[mt], bh[0], bh[1]);
                    mma_bf16(acc[mt][2*p+1], ah[mt], bh[2], bh[3]);
                }
                #pragma unroll
                for (int mt = 0; mt < 2; mt++) {
                    mma_bf16(acc[mt][2*p],   ah[mt], bl[0], bl[1]);
                    mma_bf16(acc[mt][2*p+1], ah[mt], bl[2], bl[3]);
                }
                #pragma unroll
                for (int mt = 0; mt < 2; mt++) {
                    mma_bf16(acc[mt][2*p],   al[mt], bh[0], bh[1]);
                    mma_bf16(acc[mt][2*p+1], al[mt], bh[2], bh[3]);
                }
            }
        }
        __syncthreads();
    }

    #pragma unroll
    for (int mt = 0; mt < 2; mt++) {
        #pragma unroll
        for (int half = 0; half < 2; half++) {
            const int m = bm + wm + mt * 16 + half * 8 + lr4;
            #pragma unroll
            for (int nt = 0; nt < 8; nt++) {
                const int n = bn + wn + nt * 8 + lc4 * 2;
                float v0 = acc[mt][nt][half * 2 + 0] + bias[n];
                float v1 = acc[mt][nt][half * 2 + 1] + bias[n + 1];
                if (MODE == 1) {
                    const int b = m >> 11, t = m & (SEQ - 1);
                    const int head = n >> 6, d = n & (DH - 1);
                    float2 v; v.x = v0; v.y = v1;
                    *(float2*)(C + (size_t)((b * NH + head) * SEQ + t) * DH + d) = v;
                } else {
                    if (MODE == 2) {
                        v0 = 0.5f * v0 * (1.f + erff(v0 * 0.70710678118654752f));
                        v1 = 0.5f * v1 * (1.f + erff(v1 * 0.70710678118654752f));
                    } else if (MODE == 3) {
                        float2 rv = *(const float2*)(res + (size_t)m * N + n);
                        v0 += rv.x; v1 += rv.y;
                    } else if (MODE == 4) {
                        const float gv = gate[m >> 11];
                        float2 xv  = *(const float2*)(res  + (size_t)m * N + n);
                        float2 x1v = *(const float2*)(res2 + (size_t)m * N + n);
                        v0 = xv.x + gv * (x1v.x + v0 - xv.x);
                        v1 = xv.y + gv * (x1v.y + v1 - xv.y);
                    }
                    float2 v; v.x = v0; v.y = v1;
                    *(float2*)(C + (size_t)m * N + n) = v;
                }
            }
        }
    }
}

// ============ Tensor-core causal flash attention ============
// CTA: 128 q-rows (8 warps x 16), kv-tiles of 64. QK^T: 3-term split bf16.
// P.V: P plain bf16, V split hi/lo (2 terms). Writes ctx in [B,T,DM] (+h*64).
#define AK_HI 0
#define AK_LO 9216
#define AV_HI 18432
#define AV_LO 27648
// row stride 144 bytes (72 bf16) for all 4 buffers; each buffer 64 rows

__global__ void __launch_bounds__(256) attn_mma(
    const float* __restrict__ Q, const float* __restrict__ K,
    const float* __restrict__ V, float* __restrict__ ctx)
{
    __shared__ __align__(16) char smem[36864];
    const uint32_t sb = smem_u32(smem);
    const int qt = blockIdx.x;          // 0..15
    const int bh = blockIdx.y;          // 0..63
    const int b = bh >> 4, h = bh & (NH - 1);
    const int tid = threadIdx.x;
    const int lane = tid & 31, wid = tid >> 5;
    const int lr4 = lane >> 2, lc4 = lane & 3;
    const int qbase = qt * 128;
    const int rw = qbase + wid * 16;    // warp's first q row

    const float* Qb = Q + (size_t)bh * SEQ * DH;
    const float* Kb = K + (size_t)bh * SEQ * DH;
    const float* Vb = V + (size_t)bh * SEQ * DH;

    // ---- load Q fragments (hi/lo), pre-scaled by 1/8 ----
    uint32_t qh[4][4], ql[4][4];
    #pragma unroll
    for (int ks = 0; ks < 4; ks++) {
        #pragma unroll
        for (int j = 0; j < 4; j++) {
            const int row = rw + lr4 + (j & 1) * 8;
            const int d   = ks * 16 + lc4 * 2 + (j >> 1) * 8;
            float2 qv = *(const float2*)(Qb + (size_t)row * DH + d);
            qv.x *= 0.125f; qv.y *= 0.125f;
            __nv_bfloat162 hi = __float22bfloat162_rn(qv);
            float2 hf = __bfloat1622float2(hi);
            __nv_bfloat162 lo = __float22bfloat162_rn(make_float2(qv.x - hf.x, qv.y - hf.y));
            qh[ks][j] = bf2_u32(hi);
            ql[ks][j] = bf2_u32(lo);
        }
    }

    float o[8][4];
    #pragma unroll
    for (int i = 0; i < 8; i++)
        #pragma unroll
        for (int j = 0; j < 4; j++) o[i][j] = 0.f;
    float m0 = -INFINITY, m1 = -INFINITY, l0 = 0.f, l1 = 0.f;

    // ldmatrix address lane components
    const int nt_row = (lane & 7) + ((lane >> 4) & 1) * 8;   // non-trans: n-row
    const int nt_col = ((lane >> 3) & 1) * 8;                // non-trans: k-col offset
    const int tr_row = (lane & 7) + ((lane >> 3) & 1) * 8;   // trans: k-row
    const int tr_col = (lane >> 4) * 8;                      // trans: n-col offset

    const int nkt = 2 * qt + 2;
    for (int kt = 0; kt < nkt; kt++) {
        const int kbase = kt * 64;
        __syncthreads();
        // ---- load K/V tile [64 kv][64 d] -> hi/lo bf16 smem (stride 72 el) ----
        #pragma unroll
        for (int i = 0; i < 4; i++) {
            const int idx = i * 256 + tid;
            const int kv = idx >> 4, d4 = idx & 15;
            const uint32_t off = (uint32_t)(kv * 144 + d4 * 8);
            float4 kk = *(const float4*)(Kb + (size_t)(kbase + kv) * DH + d4 * 4);
            __nv_bfloat162 h0 = __float22bfloat162_rn(make_float2(kk.x, kk.y));
            __nv_bfloat162 h1 = __float22bfloat162_rn(make_float2(kk.z, kk.w));
            float2 hf0 = __bfloat1622float2(h0), hf1 = __bfloat1622float2(h1);
            __nv_bfloat162 lo0 = __float22bfloat162_rn(make_float2(kk.x - hf0.x, kk.y - hf0.y));
            __nv_bfloat162 lo1 = __float22bfloat162_rn(make_float2(kk.z - hf1.x, kk.w - hf1.y));
            *(uint2*)(smem + AK_HI + off) = make_uint2(bf2_u32(h0), bf2_u32(h1));
            *(uint2*)(smem + AK_LO + off) = make_uint2(bf2_u32(lo0), bf2_u32(lo1));
            float4 vv = *(const float4*)(Vb + (size_t)(kbase + kv) * DH + d4 * 4);
            h0 = __float22bfloat162_rn(make_float2(vv.x, vv.y));
            h1 = __float22bfloat162_rn(make_float2(vv.z, vv.w));
            hf0 = __bfloat1622float2(h0); hf1 = __bfloat1622float2(h1);
            lo0 = __float22bfloat162_rn(make_float2(vv.x - hf0.x, vv.y - hf0.y));
            lo1 = __float22bfloat162_rn(make_float2(vv.z - hf1.x, vv.w - hf1.y));
            *(uint2*)(smem + AV_HI + off) = make_uint2(bf2_u32(h0), bf2_u32(h1));
            *(uint2*)(smem + AV_LO + off) = make_uint2(bf2_u32(lo0), bf2_u32(lo1));
        }
        __syncthreads();

        if (kbase >= rw + 16) continue;   // fully masked for this warp

        // ---- S = Q K^T (split 3-term) ----
        float s[8][4];
        #pragma unroll
        for (int i = 0; i < 8; i++)
            #pragma unroll
            for (int j = 0; j < 4; j++) s[i][j] = 0.f;
        #pragma unroll
        for (int ks = 0; ks < 4; ks++) {
            #pragma unroll
            for (int nb2 = 0; nb2 < 4; nb2++) {
                const uint32_t kaddr = sb + AK_HI
                    + (uint32_t)((nb2 * 16 + nt_row) * 144 + (ks * 16 + nt_col) * 2);
                uint32_t kh[4], kl[4];
                ldmatrix_x4(kh, kaddr);
                ldmatrix_x4(kl, kaddr + (AK_LO - AK_HI));
                mma_bf16(s[nb2*2],   qh[ks], kh[0], kh[1]);
                mma_bf16(s[nb2*2+1], qh[ks], kh[2], kh[3]);
                mma_bf16(s[nb2*2],   qh[ks], kl[0], kl[1]);
                mma_bf16(s[nb2*2+1], qh[ks], kl[2], kl[3]);
                mma_bf16(s[nb2*2],   ql[ks], kh[0], kh[1]);
                mma_bf16(s[nb2*2+1], ql[ks], kh[2], kh[3]);
            }
        }
        // ---- causal mask (diagonal tiles only) ----
        if (kbase + 63 > rw) {
            #pragma unroll
            for (int nb = 0; nb < 8; nb++)
                #pragma unroll
                for (int j = 0; j < 4; j++) {
                    const int qrow = rw + lr4 + (j >> 1) * 8;
                    const int kv = kbase + nb * 8 + lc4 * 2 + (j & 1);
                    if (kv > qrow) s[nb][j] = -INFINITY;
                }
        }
        // ---- online softmax ----
        float mx0 = -INFINITY, mx1 = -INFINITY;
        #pragma unroll
        for (int nb = 0; nb < 8; nb++) {
            mx0 = fmaxf(mx0, fmaxf(s[nb][0], s[nb][1]));
            mx1 = fmaxf(mx1, fmaxf(s[nb][2], s[nb][3]));
        }
        #pragma unroll
        for (int off = 1; off <= 2; off <<= 1) {
            mx0 = fmaxf(mx0, __shfl_xor_sync(0xffffffffu, mx0, off));
            mx1 = fmaxf(mx1, __shfl_xor_sync(0xffffffffu, mx1, off));
        }
        const float mn0 = fmaxf(m0, mx0), mn1 = fmaxf(m1, mx1);
        const float c0 = __expf(m0 - mn0), c1 = __expf(m1 - mn1);
        m0 = mn0; m1 = mn1;
        float rs0 = 0.f, rs1 = 0.f;
        #pragma unroll
        for (int nb = 0; nb < 8; nb++) {
            s[nb][0] = __expf(s[nb][0] - mn0);
            s[nb][1] = __expf(s[nb][1] - mn0);
            s[nb][2] = __expf(s[nb][2] - mn1);
            s[nb][3] = __expf(s[nb][3] - mn1);
            rs0 += s[nb][0] + s[nb][1];
            rs1 += s[nb][2] + s[nb][3];
        }
        #pragma unroll
        for (int off = 1; off <= 2; off <<= 1) {
            rs0 += __shfl_xor_sync(0xffffffffu, rs0, off);
            rs1 += __shfl_xor_sync(0xffffffffu, rs1, off);
        }
        l0 = l0 * c0 + rs0;
        l1 = l1 * c1 + rs1;
        #pragma unroll
        for (int nb = 0; nb < 8; nb++) {
            o[nb][0] *= c0; o[nb][1] *= c0;
            o[nb][2] *= c1; o[nb][3] *= c1;
        }
        // ---- pack P to bf16 A-fragments (no shuffles needed) ----
        uint32_t pa[4][4];
        #pragma unroll
        for (int ks = 0; ks < 4; ks++) {
            pa[ks][0] = bf2_u32(__float22bfloat162_rn(make_float2(s[2*ks][0],   s[2*ks][1])));
            pa[ks][1] = bf2_u32(__float22bfloat162_rn(make_float2(s[2*ks][2],   s[2*ks][3])));
            pa[ks][2] = bf2_u32(__float22bfloat162_rn(make_float2(s[2*ks+1][0], s[2*ks+1][1])));
            pa[ks][3] = bf2_u32(__float22bfloat162_rn(make_float2(s[2*ks+1][2], s[2*ks+1][3])));
        }
        // ---- O += P V (V split 2-term) ----
        #pragma unroll
        for (int ks = 0; ks < 4; ks++) {
            #pragma unroll
            for (int db2 = 0; db2 < 4; db2++) {
                const uint32_t vaddr = sb + AV_HI
                    + (uint32_t)((ks * 16 + tr_row) * 144 + (db2 * 16 + tr_col) * 2);
                uint32_t vh[4], vl[4];
                ldmatrix_x4t(vh, vaddr);
                ldmatrix_x4t(vl, vaddr + (AV_LO - AV_HI));
                mma_bf16(o[db2*2],   pa[ks], vh[0], vh[1]);
                mma_bf16(o[db2*2+1], pa[ks], vh[2], vh[3]);
                mma_bf16(o[db2*2],   pa[ks], vl[0], vl[1]);
                mma_bf16(o[db2*2+1], pa[ks], vl[2], vl[3]);
            }
        }
    }

    // ---- finalize + store ctx [B,T,DM] ----
    const float i0 = 1.f / l0, i1 = 1.f / l1;
    #pragma unroll
    for (int nb = 0; nb < 8; nb++) {
        const int d = h * DH + nb * 8 + lc4 * 2;
        {
            const int row = rw + lr4;
            float2 v; v.x = o[nb][0] * i0; v.y = o[nb][1] * i0;
            *(float2*)(ctx + (size_t)(b * SEQ + row) * DM + d) = v;
        }
        {
            const int row = rw + lr4 + 8;
            float2 v; v.x = o[nb][2] * i1; v.y = o[nb][3] * i1;
            *(float2*)(ctx + (size_t)(b * SEQ + row) * DM + d) = v;
        }
    }
}

// ---------------- launch ----------------
extern "C" void kernel_launch(void* const* d_in, const int* in_sizes, int n_in,
                              void* d_out, int out_size)
{
    const float* x      = (const float*)d_in[0];
    const float* gate   = (const float*)d_in[1];
    const float* Wq     = (const float*)d_in[2];
    const float* bq     = (const float*)d_in[3];
    const float* Wk     = (const float*)d_in[4];
    const float* bk     = (const float*)d_in[5];
    const float* Wv     = (const float*)d_in[6];
    const float* bv     = (const float*)d_in[7];
    const float* Wo     = (const float*)d_in[8];
    const float* bo     = (const float*)d_in[9];
    const float* W1     = (const float*)d_in[10];
    const float* b1     = (const float*)d_in[11];
    const float* W2     = (const float*)d_in[12];
    const float* b2     = (const float*)d_in[13];
    const float* gamma1 = (const float*)d_in[14];
    const float* beta1  = (const float*)d_in[15];
    const float* gamma2 = (const float*)d_in[16];
    const float* beta2  = (const float*)d_in[17];
    float* out = (float*)d_out;

    float *h, *q, *k, *v, *ctx, *x1, *ff;
    cudaGetSymbolAddress((void**)&h,   g_h);
    cudaGetSymbolAddress((void**)&q,   g_q);
    cudaGetSymbolAddress((void**)&k,   g_k);
    cudaGetSymbolAddress((void**)&v,   g_v);
    cudaGetSymbolAddress((void**)&ctx, g_ctx);
    cudaGetSymbolAddress((void**)&x1,  g_x1);
    cudaGetSymbolAddress((void**)&ff,  g_ff);

    cudaFuncSetAttribute(mma_gemm<1>, cudaFuncAttributeMaxDynamicSharedMemorySize, SMEM_BYTES);
    cudaFuncSetAttribute(mma_gemm<2>, cudaFuncAttributeMaxDynamicSharedMemorySize, SMEM_BYTES);
    cudaFuncSetAttribute(mma_gemm<3>, cudaFuncAttributeMaxDynamicSharedMemorySize, SMEM_BYTES);
    cudaFuncSetAttribute(mma_gemm<4>, cudaFuncAttributeMaxDynamicSharedMemorySize, SMEM_BYTES);

    // 1. h = LN(x)
    ln_kernel<<<MROWS, 256>>>(x, gamma1, beta1, h);

    // 2. Q/K/V projections with fused [B,H,T,D] relayout
    dim3 g1(DM/128, MROWS/128);
    mma_gemm<1><<<g1, 256, SMEM_BYTES>>>(h, Wq, bq, q, MROWS, DM, DM, nullptr, nullptr, nullptr);
    mma_gemm<1><<<g1, 256, SMEM_BYTES>>>(h, Wk, bk, k, MROWS, DM, DM, nullptr, nullptr, nullptr);
    mma_gemm<1><<<g1, 256, SMEM_BYTES>>>(h, Wv, bv, v, MROWS, DM, DM, nullptr, nullptr, nullptr);

    // 3. causal attention -> ctx [B,T,C]  (tensor cores)
    attn_mma<<<dim3(SEQ/128, BATCH*NH), 256>>>(q, k, v, ctx);

    // 4. x1 = ctx@Wo + bo + x
    mma_gemm<3><<<g1, 256, SMEM_BYTES>>>(ctx, Wo, bo, x1, MROWS, DM, DM, x, nullptr, nullptr);

    // 5. h = LN(x1)
    ln_kernel<<<MROWS, 256>>>(x1, gamma2, beta2, h);

    // 6. ff = GELU(h@W1 + b1)
    mma_gemm<2><<<dim3(DFF/128, MROWS/128), 256, SMEM_BYTES>>>(h, W1, b1, ff, MROWS, DFF, DM,
                                                               nullptr, nullptr, nullptr);

    // 7. out = x + g*(x1 + (ff@W2 + b2) - x)
    mma_gemm<4><<<g1, 256, SMEM_BYTES>>>(ff, W2, b2, out, MROWS, DM, DFF, x, x1, gate);
}